// round 8
// baseline (speedup 1.0000x reference)
#include <cuda_runtime.h>
#include <cstdint>

// ---------------- problem constants ----------------
#define B_LON 30
#define NW    32
#define NTOK  144
#define CDIM  192
#define NH    6
#define HD    32
#define NBW   (B_LON * NW)          // 960
#define SCALE 0.17677669529663687f  // 1/sqrt(32)

// smem strides (floats). All ≡ 8 (mod 32) -> conflict-free LDS.64 fragment loads.
#define SXS 200   // x / weight rows (K=192 permuted cols)
#define QVS 40    // q/k rows       (K=32 permuted cols)
#define SAS 152   // score rows     (144 permuted cols)
#define VTS 168   // v^T rows (d-major, 144 permuted cols)

// ---------------- scratch (device globals; no allocs allowed) ----------------
__device__ float g_q[NBW * NH * NTOK * HD];     // pre-scaled, tf32-rounded, [bw][h][n][d]
__device__ float g_k[NBW * NH * NTOK * HD];
__device__ float g_v[NBW * NH * NTOK * HD];
__device__ float g_o[NBW * NTOK * CDIM];        // attention output, [bw][n][c]
__device__ float g_bias[CDIM * NTOK * NTOK];    // dense bias, [(w*6+h)][n][m]

// ---------------- helpers ----------------
__device__ __forceinline__ uint32_t f2tf(float x) {
    uint32_t r; asm("cvt.rna.tf32.f32 %0, %1;" : "=r"(r) : "f"(x)); return r;
}
__device__ __forceinline__ float f2tff(float x) {
    return __uint_as_float(f2tf(x));
}
// permute col c within its 8-group: logical c -> [0,2,4,6,1,3,5,7][index] so that
// positions (2t, 2t+1) hold logical (t, t+4) — one float2 per tf32 fragment pair.
__device__ __forceinline__ int kperm(int c) {
    return (c & ~7) | ((c & 3) << 1) | ((c >> 2) & 1);
}
__device__ __forceinline__ void mma_tf32(float c[4], uint32_t a0, uint32_t a1,
                                         uint32_t a2, uint32_t a3,
                                         uint32_t b0, uint32_t b1) {
    asm volatile(
        "mma.sync.aligned.m16n8k8.row.col.f32.tf32.tf32.f32 "
        "{%0,%1,%2,%3}, {%4,%5,%6,%7}, {%8,%9}, {%0,%1,%2,%3};\n"
        : "+f"(c[0]), "+f"(c[1]), "+f"(c[2]), "+f"(c[3])
        : "r"(a0), "r"(a1), "r"(a2), "r"(a3), "r"(b0), "r"(b1));
}

// ---------------- kernel 0: densify earth-position bias ----------------
__global__ __launch_bounds__(256) void bias_pre_kernel(
    const float* __restrict__ table, const int* __restrict__ pos) {
    __shared__ float sm[CDIM * 33];
    __shared__ int sidx[32];
    int p0 = blockIdx.x * 32;
    int tid = threadIdx.x;
    if (tid < 32) sidx[tid] = pos[p0 + tid];
    __syncthreads();
    for (int i = tid; i < 32 * CDIM; i += 256) {
        int p = i / CDIM, whc = i % CDIM;
        sm[whc * 33 + p] = table[(long)sidx[p] * CDIM + whc];
    }
    __syncthreads();
    for (int i = tid; i < 32 * CDIM; i += 256) {
        int wh = i / 32, p = i % 32;
        g_bias[(long)wh * (NTOK * NTOK) + p0 + p] = sm[wh * 33 + p];
    }
}

// ---------------- kernel 1: QKV projection (tf32 MMA, paired LDS.64) ----------------
__global__ __launch_bounds__(288, 1) void qkv_kernel(
    const float* __restrict__ x, const float* __restrict__ wt,
    const float* __restrict__ bias) {
    extern __shared__ float sm[];
    float* sx = sm;                 // 144 x SXS, tf32-rounded, K-permuted
    float* sw = sm + NTOK * SXS;    // 64 x SXS
    int bw = blockIdx.x;
    int tid = threadIdx.x;
    int warp = tid >> 5, lane = tid & 31, gp = lane >> 2, tg = lane & 3;
    int m0 = warp * 16;

    const float* xp = x + (long)bw * NTOK * CDIM;
    for (int i = tid; i < NTOK * CDIM / 4; i += 288) {
        int e = i * 4;
        int n = e / CDIM, k = e % CDIM;
        float4 v = *(const float4*)(xp + e);
        float* d = sx + n * SXS + (k & ~7) + ((k >> 2) & 1);
        d[0] = f2tff(v.x); d[2] = f2tff(v.y); d[4] = f2tff(v.z); d[6] = f2tff(v.w);
    }

    for (int ct = 0; ct < 9; ++ct) {
        __syncthreads();
        int c0 = ct * 64;
        for (int i = tid; i < 64 * CDIM / 4; i += 288) {
            int e = i * 4;
            int j = e / CDIM, k = e % CDIM;
            float4 v = *(const float4*)(wt + (long)(c0 + j) * CDIM + k);
            float* d = sw + j * SXS + (k & ~7) + ((k >> 2) & 1);
            d[0] = f2tff(v.x); d[2] = f2tff(v.y); d[4] = f2tff(v.z); d[6] = f2tff(v.w);
        }
        __syncthreads();
        float acc[8][4];
#pragma unroll
        for (int t = 0; t < 8; t++)
#pragma unroll
            for (int j = 0; j < 4; j++) acc[t][j] = 0.f;
#pragma unroll
        for (int kk = 0; kk < 24; ++kk) {
            int k0 = kk * 8;
            float2 pa0 = *(const float2*)(sx + (m0 + gp) * SXS + k0 + 2 * tg);
            float2 pa1 = *(const float2*)(sx + (m0 + gp + 8) * SXS + k0 + 2 * tg);
            uint32_t a0 = __float_as_uint(pa0.x), a2 = __float_as_uint(pa0.y);
            uint32_t a1 = __float_as_uint(pa1.x), a3 = __float_as_uint(pa1.y);
#pragma unroll
            for (int t = 0; t < 8; ++t) {
                float2 pb = *(const float2*)(sw + (t * 8 + gp) * SXS + k0 + 2 * tg);
                mma_tf32(acc[t], a0, a1, a2, a3,
                         __float_as_uint(pb.x), __float_as_uint(pb.y));
            }
        }
        // epilogue: bias, q-scale, tf32 round, head-major scatter
#pragma unroll
        for (int t = 0; t < 8; ++t) {
#pragma unroll
            for (int cc = 0; cc < 2; ++cc) {
                int col = c0 + t * 8 + 2 * tg + cc;
                int s = col / CDIM, rem = col % CDIM;
                int h = rem / HD, d = rem & (HD - 1);
                float bb = bias[col];
                float mul = (s == 0) ? SCALE : 1.f;
                float* dst = (s == 0) ? g_q : (s == 1) ? g_k : g_v;
                float* base = dst + (long)(bw * NH + h) * NTOK * HD + d;
                base[(m0 + gp) * HD]     = f2tff((acc[t][cc]     + bb) * mul);
                base[(m0 + gp + 8) * HD] = f2tff((acc[t][2 + cc] + bb) * mul);
            }
        }
    }
}

// ---------------- kernel 2: fused attention per (b,w,h) ----------------
__global__ __launch_bounds__(288, 1) void attn_kernel(const float* __restrict__ mask) {
    extern __shared__ float sm[];
    float* sq  = sm;                      // 144 x QVS (d-permuted)
    float* sk  = sq + NTOK * QVS;         // 144 x QVS
    float* svt = sk + NTOK * QVS;         // 32 x VTS  (v^T, m-permuted)
    float* sa  = svt + HD * VTS;          // 144 x SAS (m-permuted)
    int h  = blockIdx.x;
    int bw = blockIdx.y;
    int w  = bw % NW;
    int tid = threadIdx.x;
    int warp = tid >> 5, lane = tid & 31, gp = lane >> 2, tg = lane & 3;
    int m0 = warp * 16;

    long base = (long)(bw * NH + h) * NTOK * HD;
    const float* qp = g_q + base;
    const float* kp = g_k + base;
    const float* vp = g_v + base;
    for (int i = tid; i < NTOK * HD / 4; i += 288) {
        int n = i >> 3, d0 = (i & 7) * 4;
        int po = n * QVS + (d0 & ~7) + ((d0 >> 2) & 1);
        float4 vq = *(const float4*)(qp + n * HD + d0);
        sq[po] = vq.x; sq[po + 2] = vq.y; sq[po + 4] = vq.z; sq[po + 6] = vq.w;
        float4 vk = *(const float4*)(kp + n * HD + d0);
        sk[po] = vk.x; sk[po + 2] = vk.y; sk[po + 4] = vk.z; sk[po + 6] = vk.w;
        float4 vv = *(const float4*)(vp + n * HD + d0);
        int pc = kperm(n);
        svt[(d0 + 0) * VTS + pc] = vv.x;
        svt[(d0 + 1) * VTS + pc] = vv.y;
        svt[(d0 + 2) * VTS + pc] = vv.z;
        svt[(d0 + 3) * VTS + pc] = vv.w;
    }
    __syncthreads();

    const float* bp = g_bias + (long)(w * NH + h) * NTOK * NTOK;
    const float* mp = mask + (long)bw * NTOK * NTOK;

    // QK^T: each warp m16 x 144, two passes of n=72
#pragma unroll
    for (int pass = 0; pass < 2; ++pass) {
        int nb = pass * 72;
        float acc[9][4];
#pragma unroll
        for (int t = 0; t < 9; t++)
#pragma unroll
            for (int j = 0; j < 4; j++) acc[t][j] = 0.f;
#pragma unroll
        for (int kk = 0; kk < 4; ++kk) {
            int k0 = kk * 8;
            float2 pa0 = *(const float2*)(sq + (m0 + gp) * QVS + k0 + 2 * tg);
            float2 pa1 = *(const float2*)(sq + (m0 + gp + 8) * QVS + k0 + 2 * tg);
            uint32_t a0 = __float_as_uint(pa0.x), a2 = __float_as_uint(pa0.y);
            uint32_t a1 = __float_as_uint(pa1.x), a3 = __float_as_uint(pa1.y);
#pragma unroll
            for (int t = 0; t < 9; ++t) {
                float2 pb = *(const float2*)(sk + (nb + t * 8 + gp) * QVS + k0 + 2 * tg);
                mma_tf32(acc[t], a0, a1, a2, a3,
                         __float_as_uint(pb.x), __float_as_uint(pb.y));
            }
        }
#pragma unroll
        for (int t = 0; t < 9; ++t) {
            int mcol = nb + t * 8 + 2 * tg;           // logical score column
            int pc0 = (mcol & ~7) + kperm(mcol & 7);  // permuted store position
            int pc1 = (mcol & ~7) + kperm((mcol & 7) + 1);
            int r0 = m0 + gp, r1 = r0 + 8;
            sa[r0 * SAS + pc0] = acc[t][0] + bp[r0 * NTOK + mcol]     + mp[r0 * NTOK + mcol];
            sa[r0 * SAS + pc1] = acc[t][1] + bp[r0 * NTOK + mcol + 1] + mp[r0 * NTOK + mcol + 1];
            sa[r1 * SAS + pc0] = acc[t][2] + bp[r1 * NTOK + mcol]     + mp[r1 * NTOK + mcol];
            sa[r1 * SAS + pc1] = acc[t][3] + bp[r1 * NTOK + mcol + 1] + mp[r1 * NTOK + mcol + 1];
        }
    }
    __syncthreads();

    // softmax: permutation-invariant (full-row max/sum, in-place)
    for (int r = warp; r < NTOK; r += 9) {
        float mx = -1e30f;
        for (int c = lane; c < NTOK; c += 32) mx = fmaxf(mx, sa[r * SAS + c]);
#pragma unroll
        for (int o = 16; o; o >>= 1) mx = fmaxf(mx, __shfl_xor_sync(0xffffffffu, mx, o));
        float s = 0.f;
        for (int c = lane; c < NTOK; c += 32) {
            float e = __expf(sa[r * SAS + c] - mx);
            sa[r * SAS + c] = e;
            s += e;
        }
#pragma unroll
        for (int o = 16; o; o >>= 1) s += __shfl_xor_sync(0xffffffffu, s, o);
        float inv = 1.f / s;
        for (int c = lane; c < NTOK; c += 32) sa[r * SAS + c] = f2tff(sa[r * SAS + c] * inv);
    }
    __syncthreads();

    // P @ V: warp m16 x 32, K=144 (A pairs from sa, B pairs from v^T)
    float acc2[4][4];
#pragma unroll
    for (int t = 0; t < 4; t++)
#pragma unroll
        for (int j = 0; j < 4; j++) acc2[t][j] = 0.f;
#pragma unroll
    for (int kk = 0; kk < 18; ++kk) {
        int k0 = kk * 8;
        float2 pa0 = *(const float2*)(sa + (m0 + gp) * SAS + k0 + 2 * tg);
        float2 pa1 = *(const float2*)(sa + (m0 + gp + 8) * SAS + k0 + 2 * tg);
        uint32_t a0 = __float_as_uint(pa0.x), a2 = __float_as_uint(pa0.y);
        uint32_t a1 = __float_as_uint(pa1.x), a3 = __float_as_uint(pa1.y);
#pragma unroll
        for (int t = 0; t < 4; ++t) {
            float2 pb = *(const float2*)(svt + (t * 8 + gp) * VTS + k0 + 2 * tg);
            mma_tf32(acc2[t], a0, a1, a2, a3,
                     __float_as_uint(pb.x), __float_as_uint(pb.y));
        }
    }
    float* op = g_o + (long)bw * NTOK * CDIM + h * HD;
#pragma unroll
    for (int t = 0; t < 4; ++t) {
        int d = t * 8 + 2 * tg;
        int r0 = m0 + gp, r1 = r0 + 8;
        op[r0 * CDIM + d]     = acc2[t][0];
        op[r0 * CDIM + d + 1] = acc2[t][1];
        op[r1 * CDIM + d]     = acc2[t][2];
        op[r1 * CDIM + d + 1] = acc2[t][3];
    }
}

// ---------------- kernel 3: output projection ----------------
__global__ __launch_bounds__(288, 1) void proj_kernel(
    const float* __restrict__ wt, const float* __restrict__ bias,
    float* __restrict__ out) {
    extern __shared__ float sm[];
    float* sx = sm;                 // 144 x SXS
    float* sw = sm + NTOK * SXS;    // 64 x SXS
    int bw = blockIdx.x;
    int tid = threadIdx.x;
    int warp = tid >> 5, lane = tid & 31, gp = lane >> 2, tg = lane & 3;
    int m0 = warp * 16;

    const float* xp = g_o + (long)bw * NTOK * CDIM;
    for (int i = tid; i < NTOK * CDIM / 4; i += 288) {
        int e = i * 4;
        int n = e / CDIM, k = e % CDIM;
        float4 v = *(const float4*)(xp + e);
        float* d = sx + n * SXS + (k & ~7) + ((k >> 2) & 1);
        d[0] = f2tff(v.x); d[2] = f2tff(v.y); d[4] = f2tff(v.z); d[6] = f2tff(v.w);
    }

    for (int ct = 0; ct < 3; ++ct) {
        __syncthreads();
        int c0 = ct * 64;
        for (int i = tid; i < 64 * CDIM / 4; i += 288) {
            int e = i * 4;
            int j = e / CDIM, k = e % CDIM;
            float4 v = *(const float4*)(wt + (long)(c0 + j) * CDIM + k);
            float* d = sw + j * SXS + (k & ~7) + ((k >> 2) & 1);
            d[0] = f2tff(v.x); d[2] = f2tff(v.y); d[4] = f2tff(v.z); d[6] = f2tff(v.w);
        }
        __syncthreads();
        float acc[8][4];
#pragma unroll
        for (int t = 0; t < 8; t++)
#pragma unroll
            for (int j = 0; j < 4; j++) acc[t][j] = 0.f;
#pragma unroll
        for (int kk = 0; kk < 24; ++kk) {
            int k0 = kk * 8;
            float2 pa0 = *(const float2*)(sx + (m0 + gp) * SXS + k0 + 2 * tg);
            float2 pa1 = *(const float2*)(sx + (m0 + gp + 8) * SXS + k0 + 2 * tg);
            uint32_t a0 = __float_as_uint(pa0.x), a2 = __float_as_uint(pa0.y);
            uint32_t a1 = __float_as_uint(pa1.x), a3 = __float_as_uint(pa1.y);
#pragma unroll
            for (int t = 0; t < 8; ++t) {
                float2 pb = *(const float2*)(sw + (t * 8 + gp) * SXS + k0 + 2 * tg);
                mma_tf32(acc[t], a0, a1, a2, a3,
                         __float_as_uint(pb.x), __float_as_uint(pb.y));
            }
        }
        float* ob = out + (long)bw * NTOK * CDIM;
#pragma unroll
        for (int t = 0; t < 8; ++t) {
#pragma unroll
            for (int cc = 0; cc < 2; ++cc) {
                int col = c0 + t * 8 + 2 * tg + cc;
                float bb = bias[col];
                ob[(m0 + gp) * CDIM + col]     = acc[t][cc]     + bb;
                ob[(m0 + gp + 8) * CDIM + col] = acc[t][2 + cc] + bb;
            }
        }
    }
}

// ---------------- launch ----------------
extern "C" void kernel_launch(void* const* d_in, const int* in_sizes, int n_in,
                              void* d_out, int out_size) {
    const float* x      = (const float*)d_in[0];
    const float* mask   = (const float*)d_in[1];
    const float* qkv_w  = (const float*)d_in[2];
    const float* qkv_b  = (const float*)d_in[3];
    const float* proj_w = (const float*)d_in[4];
    const float* proj_b = (const float*)d_in[5];
    const float* table  = (const float*)d_in[6];
    const int*   pos    = (const int*)d_in[7];
    float* out = (float*)d_out;

    const int lin_smem  = (NTOK * SXS + 64 * SXS) * 4;                      // 166400 B
    const int attn_smem = (2 * NTOK * QVS + HD * VTS + NTOK * SAS) * 4;    // 155136 B
    cudaFuncSetAttribute(qkv_kernel,  cudaFuncAttributeMaxDynamicSharedMemorySize, lin_smem);
    cudaFuncSetAttribute(proj_kernel, cudaFuncAttributeMaxDynamicSharedMemorySize, lin_smem);
    cudaFuncSetAttribute(attn_kernel, cudaFuncAttributeMaxDynamicSharedMemorySize, attn_smem);

    bias_pre_kernel<<<(NTOK * NTOK) / 32, 256>>>(table, pos);
    qkv_kernel<<<NBW, 288, lin_smem>>>(x, qkv_w, qkv_b);
    attn_kernel<<<dim3(NH, NBW), 288, attn_smem>>>(mask);
    proj_kernel<<<NBW, 288, lin_smem>>>(proj_w, proj_b, out);
}

// round 9
// speedup vs baseline: 1.5262x; 1.5262x over previous
#include <cuda_runtime.h>
#include <cstdint>

// ---------------- problem constants ----------------
#define B_LON 30
#define NW    32
#define NTOK  144
#define CDIM  192
#define NH    6
#define HD    32
#define NBW   (B_LON * NW)          // 960
#define SCALE 0.17677669529663687f  // 1/sqrt(32)

#define SXS 200   // x smem stride (K-permuted pairs), ≡8 mod 32 -> conflict-free LDS.64
#define QVS 40    // q/k/v smem stride (natural, R3 layout)
#define SAS 148   // score smem stride (natural, R3 layout)

// ---------------- scratch (device globals; no allocs allowed) ----------------
__device__ float g_q[NBW * NH * NTOK * HD];     // pre-scaled, tf32-rounded, [bw][h][n][d]
__device__ float g_k[NBW * NH * NTOK * HD];
__device__ float g_v[NBW * NH * NTOK * HD];
__device__ float g_o[NBW * NTOK * CDIM];        // attention output, [bw][n][c]
__device__ float g_bias[CDIM * NTOK * NTOK];    // dense bias, [(w*6+h)][n][m]
__device__ float g_wqkv[576 * CDIM];            // fragment-direct qkv weights (tf32)
__device__ float g_wproj[CDIM * CDIM];          // fragment-direct proj weights (tf32)

// ---------------- helpers ----------------
__device__ __forceinline__ uint32_t f2tf(float x) {
    uint32_t r; asm("cvt.rna.tf32.f32 %0, %1;" : "=r"(r) : "f"(x)); return r;
}
__device__ __forceinline__ float f2tff(float x) {
    return __uint_as_float(f2tf(x));
}
__device__ __forceinline__ void mma_tf32(float c[4], uint32_t a0, uint32_t a1,
                                         uint32_t a2, uint32_t a3,
                                         uint32_t b0, uint32_t b1) {
    asm volatile(
        "mma.sync.aligned.m16n8k8.row.col.f32.tf32.tf32.f32 "
        "{%0,%1,%2,%3}, {%4,%5,%6,%7}, {%8,%9}, {%0,%1,%2,%3};\n"
        : "+f"(c[0]), "+f"(c[1]), "+f"(c[2]), "+f"(c[3])
        : "r"(a0), "r"(a1), "r"(a2), "r"(a3), "r"(b0), "r"(b1));
}

// ---------------- kernel 0a: densify earth-position bias ----------------
__global__ __launch_bounds__(256) void bias_pre_kernel(
    const float* __restrict__ table, const int* __restrict__ pos) {
    __shared__ float sm[CDIM * 33];
    __shared__ int sidx[32];
    int p0 = blockIdx.x * 32;
    int tid = threadIdx.x;
    if (tid < 32) sidx[tid] = pos[p0 + tid];
    __syncthreads();
    for (int i = tid; i < 32 * CDIM; i += 256) {
        int p = i / CDIM, whc = i % CDIM;
        sm[whc * 33 + p] = table[(long)sidx[p] * CDIM + whc];
    }
    __syncthreads();
    for (int i = tid; i < 32 * CDIM; i += 256) {
        int wh = i / 32, p = i % 32;
        g_bias[(long)wh * (NTOK * NTOK) + p0 + p] = sm[wh * 33 + p];
    }
}

// ---------------- kernel 0b: pre-permute weights into fragment-direct layout ----------
// dst float2 index idx = (((ct*24+kk)*8+t)*8+gp)*4+tg holds
//   { tf32(W[c][k+tg]), tf32(W[c][k+tg+4]) }, c = ct*64+t*8+gp, k = kk*8.
__global__ __launch_bounds__(256) void wperm_kernel(
    const float* __restrict__ wt, float* __restrict__ dst, int nct) {
    int idx = blockIdx.x * 256 + threadIdx.x;
    int total = nct * 24 * 8 * 8 * 4;
    if (idx >= total) return;
    int tg = idx & 3;
    int r  = idx >> 2;
    int gp = r & 7;  r >>= 3;
    int t  = r & 7;  r >>= 3;
    int kk = r % 24;
    int ct = r / 24;
    int col = ct * 64 + t * 8 + gp;
    int k   = kk * 8 + tg;
    dst[idx * 2]     = f2tff(wt[(long)col * CDIM + k]);
    dst[idx * 2 + 1] = f2tff(wt[(long)col * CDIM + k + 4]);
}

// ---------------- kernel 1: QKV projection (A from smem, B direct from L2) ----------
__global__ __launch_bounds__(288, 1) void qkv_kernel(
    const float* __restrict__ x, const float* __restrict__ bias) {
    extern __shared__ float sm[];
    float* sx = sm;                 // 144 x SXS, tf32-rounded, K-pair-permuted
    int bw = blockIdx.x;
    int tid = threadIdx.x;
    int warp = tid >> 5, lane = tid & 31, gp = lane >> 2, tg = lane & 3;
    int m0 = warp * 16;

    const float* xp = x + (long)bw * NTOK * CDIM;
    for (int i = tid; i < NTOK * CDIM / 4; i += 288) {
        int e = i * 4;
        int n = e / CDIM, k = e % CDIM;
        float4 v = *(const float4*)(xp + e);
        float* d = sx + n * SXS + (k & ~7) + ((k >> 2) & 1);
        d[0] = f2tff(v.x); d[2] = f2tff(v.y); d[4] = f2tff(v.z); d[6] = f2tff(v.w);
    }
    __syncthreads();

    const float2* wq = (const float2*)g_wqkv;
    for (int ct = 0; ct < 9; ++ct) {
        float acc[8][4];
#pragma unroll
        for (int t = 0; t < 8; t++)
#pragma unroll
            for (int j = 0; j < 4; j++) acc[t][j] = 0.f;
#pragma unroll 4
        for (int kk = 0; kk < 24; ++kk) {
            int k0 = kk * 8;
            float2 pa0 = *(const float2*)(sx + (m0 + gp) * SXS + k0 + 2 * tg);
            float2 pa1 = *(const float2*)(sx + (m0 + gp + 8) * SXS + k0 + 2 * tg);
            uint32_t a0 = __float_as_uint(pa0.x), a2 = __float_as_uint(pa0.y);
            uint32_t a1 = __float_as_uint(pa1.x), a3 = __float_as_uint(pa1.y);
            const float2* wb = wq + (ct * 24 + kk) * 256 + lane;
#pragma unroll
            for (int t = 0; t < 8; ++t) {
                float2 pb = __ldg(wb + t * 32);
                mma_tf32(acc[t], a0, a1, a2, a3,
                         __float_as_uint(pb.x), __float_as_uint(pb.y));
            }
        }
        int c0 = ct * 64;
#pragma unroll
        for (int t = 0; t < 8; ++t) {
#pragma unroll
            for (int cc = 0; cc < 2; ++cc) {
                int col = c0 + t * 8 + 2 * tg + cc;
                int s = col / CDIM, rem = col % CDIM;
                int h = rem / HD, d = rem & (HD - 1);
                float bb = bias[col];
                float mul = (s == 0) ? SCALE : 1.f;
                float* dst = (s == 0) ? g_q : (s == 1) ? g_k : g_v;
                float* base = dst + (long)(bw * NH + h) * NTOK * HD + d;
                base[(m0 + gp) * HD]     = f2tff((acc[t][cc]     + bb) * mul);
                base[(m0 + gp + 8) * HD] = f2tff((acc[t][2 + cc] + bb) * mul);
            }
        }
    }
}

// ---------------- kernel 2: fused attention per (b,w,h) — R3 version ----------------
__global__ __launch_bounds__(288, 1) void attn_kernel(const float* __restrict__ mask) {
    extern __shared__ float sm[];
    float* sq = sm;                      // 144 x QVS
    float* sk = sq + NTOK * QVS;
    float* sv = sk + NTOK * QVS;
    float* sa = sv + NTOK * QVS;         // 144 x SAS
    int h  = blockIdx.x;
    int bw = blockIdx.y;
    int w  = bw % NW;
    int tid = threadIdx.x;
    int warp = tid >> 5, lane = tid & 31, gp = lane >> 2, tg = lane & 3;
    int m0 = warp * 16;

    long base = (long)(bw * NH + h) * NTOK * HD;
    const float* qp = g_q + base;
    const float* kp = g_k + base;
    const float* vp = g_v + base;
    for (int i = tid; i < NTOK * HD / 4; i += 288) {
        int n = i >> 3, d = (i & 7) * 4;
        *(float4*)(sq + n * QVS + d) = *(const float4*)(qp + n * HD + d);
        *(float4*)(sk + n * QVS + d) = *(const float4*)(kp + n * HD + d);
        *(float4*)(sv + n * QVS + d) = *(const float4*)(vp + n * HD + d);
    }
    __syncthreads();

    const float* bp = g_bias + (long)(w * NH + h) * NTOK * NTOK;
    const float* mp = mask + (long)bw * NTOK * NTOK;

#pragma unroll
    for (int pass = 0; pass < 2; ++pass) {
        int nb = pass * 72;
        float acc[9][4];
#pragma unroll
        for (int t = 0; t < 9; t++)
#pragma unroll
            for (int j = 0; j < 4; j++) acc[t][j] = 0.f;
#pragma unroll
        for (int kk = 0; kk < 4; ++kk) {
            int k = kk * 8;
            const float* ab = sq + (m0 + gp) * QVS + k + tg;
            uint32_t a0 = __float_as_uint(ab[0]);
            uint32_t a1 = __float_as_uint(ab[8 * QVS]);
            uint32_t a2 = __float_as_uint(ab[4]);
            uint32_t a3 = __float_as_uint(ab[8 * QVS + 4]);
#pragma unroll
            for (int t = 0; t < 9; ++t) {
                const float* bb = sk + (nb + t * 8 + gp) * QVS + k + tg;
                mma_tf32(acc[t], a0, a1, a2, a3,
                         __float_as_uint(bb[0]), __float_as_uint(bb[4]));
            }
        }
#pragma unroll
        for (int t = 0; t < 9; ++t) {
            int mcol = nb + t * 8 + 2 * tg;
            int r0 = m0 + gp, r1 = r0 + 8;
            sa[r0 * SAS + mcol]     = acc[t][0] + bp[r0 * NTOK + mcol]     + mp[r0 * NTOK + mcol];
            sa[r0 * SAS + mcol + 1] = acc[t][1] + bp[r0 * NTOK + mcol + 1] + mp[r0 * NTOK + mcol + 1];
            sa[r1 * SAS + mcol]     = acc[t][2] + bp[r1 * NTOK + mcol]     + mp[r1 * NTOK + mcol];
            sa[r1 * SAS + mcol + 1] = acc[t][3] + bp[r1 * NTOK + mcol + 1] + mp[r1 * NTOK + mcol + 1];
        }
    }
    __syncthreads();

    for (int r = warp; r < NTOK; r += 9) {
        float mx = -1e30f;
        for (int c = lane; c < NTOK; c += 32) mx = fmaxf(mx, sa[r * SAS + c]);
#pragma unroll
        for (int o = 16; o; o >>= 1) mx = fmaxf(mx, __shfl_xor_sync(0xffffffffu, mx, o));
        float s = 0.f;
        for (int c = lane; c < NTOK; c += 32) {
            float e = __expf(sa[r * SAS + c] - mx);
            sa[r * SAS + c] = e;
            s += e;
        }
#pragma unroll
        for (int o = 16; o; o >>= 1) s += __shfl_xor_sync(0xffffffffu, s, o);
        float inv = 1.f / s;
        for (int c = lane; c < NTOK; c += 32) sa[r * SAS + c] = f2tff(sa[r * SAS + c] * inv);
    }
    __syncthreads();

    float acc2[4][4];
#pragma unroll
    for (int t = 0; t < 4; t++)
#pragma unroll
        for (int j = 0; j < 4; j++) acc2[t][j] = 0.f;
#pragma unroll
    for (int kk = 0; kk < 18; ++kk) {
        int k = kk * 8;
        const float* ab = sa + (m0 + gp) * SAS + k + tg;
        uint32_t a0 = __float_as_uint(ab[0]);
        uint32_t a1 = __float_as_uint(ab[8 * SAS]);
        uint32_t a2 = __float_as_uint(ab[4]);
        uint32_t a3 = __float_as_uint(ab[8 * SAS + 4]);
#pragma unroll
        for (int t = 0; t < 4; ++t) {
            const float* bb = sv + (k + tg) * QVS + t * 8 + gp;
            mma_tf32(acc2[t], a0, a1, a2, a3,
                     __float_as_uint(bb[0]), __float_as_uint(bb[4 * QVS]));
        }
    }
    float* op = g_o + (long)bw * NTOK * CDIM + h * HD;
#pragma unroll
    for (int t = 0; t < 4; ++t) {
        int d = t * 8 + 2 * tg;
        int r0 = m0 + gp, r1 = r0 + 8;
        op[r0 * CDIM + d]     = acc2[t][0];
        op[r0 * CDIM + d + 1] = acc2[t][1];
        op[r1 * CDIM + d]     = acc2[t][2];
        op[r1 * CDIM + d + 1] = acc2[t][3];
    }
}

// ---------------- kernel 3: output projection (A from smem, B direct from L2) ------
__global__ __launch_bounds__(288, 1) void proj_kernel(
    const float* __restrict__ bias, float* __restrict__ out) {
    extern __shared__ float sm[];
    float* sx = sm;                 // 144 x SXS
    int bw = blockIdx.x;
    int tid = threadIdx.x;
    int warp = tid >> 5, lane = tid & 31, gp = lane >> 2, tg = lane & 3;
    int m0 = warp * 16;

    const float* xp = g_o + (long)bw * NTOK * CDIM;
    for (int i = tid; i < NTOK * CDIM / 4; i += 288) {
        int e = i * 4;
        int n = e / CDIM, k = e % CDIM;
        float4 v = *(const float4*)(xp + e);
        float* d = sx + n * SXS + (k & ~7) + ((k >> 2) & 1);
        d[0] = f2tff(v.x); d[2] = f2tff(v.y); d[4] = f2tff(v.z); d[6] = f2tff(v.w);
    }
    __syncthreads();

    const float2* wp = (const float2*)g_wproj;
    for (int ct = 0; ct < 3; ++ct) {
        float acc[8][4];
#pragma unroll
        for (int t = 0; t < 8; t++)
#pragma unroll
            for (int j = 0; j < 4; j++) acc[t][j] = 0.f;
#pragma unroll 4
        for (int kk = 0; kk < 24; ++kk) {
            int k0 = kk * 8;
            float2 pa0 = *(const float2*)(sx + (m0 + gp) * SXS + k0 + 2 * tg);
            float2 pa1 = *(const float2*)(sx + (m0 + gp + 8) * SXS + k0 + 2 * tg);
            uint32_t a0 = __float_as_uint(pa0.x), a2 = __float_as_uint(pa0.y);
            uint32_t a1 = __float_as_uint(pa1.x), a3 = __float_as_uint(pa1.y);
            const float2* wb = wp + (ct * 24 + kk) * 256 + lane;
#pragma unroll
            for (int t = 0; t < 8; ++t) {
                float2 pb = __ldg(wb + t * 32);
                mma_tf32(acc[t], a0, a1, a2, a3,
                         __float_as_uint(pb.x), __float_as_uint(pb.y));
            }
        }
        int c0 = ct * 64;
        float* ob = out + (long)bw * NTOK * CDIM;
#pragma unroll
        for (int t = 0; t < 8; ++t) {
#pragma unroll
            for (int cc = 0; cc < 2; ++cc) {
                int col = c0 + t * 8 + 2 * tg + cc;
                float bb = bias[col];
                ob[(m0 + gp) * CDIM + col]     = acc[t][cc]     + bb;
                ob[(m0 + gp + 8) * CDIM + col] = acc[t][2 + cc] + bb;
            }
        }
    }
}

// ---------------- launch ----------------
extern "C" void kernel_launch(void* const* d_in, const int* in_sizes, int n_in,
                              void* d_out, int out_size) {
    const float* x      = (const float*)d_in[0];
    const float* mask   = (const float*)d_in[1];
    const float* qkv_w  = (const float*)d_in[2];
    const float* qkv_b  = (const float*)d_in[3];
    const float* proj_w = (const float*)d_in[4];
    const float* proj_b = (const float*)d_in[5];
    const float* table  = (const float*)d_in[6];
    const int*   pos    = (const int*)d_in[7];
    float* out = (float*)d_out;

    const int lin_smem  = NTOK * SXS * 4;                                  // 115200 B
    const int attn_smem = (3 * NTOK * QVS + NTOK * SAS) * 4;               // 154368 B
    cudaFuncSetAttribute(qkv_kernel,  cudaFuncAttributeMaxDynamicSharedMemorySize, lin_smem);
    cudaFuncSetAttribute(proj_kernel, cudaFuncAttributeMaxDynamicSharedMemorySize, lin_smem);
    cudaFuncSetAttribute(attn_kernel, cudaFuncAttributeMaxDynamicSharedMemorySize, attn_smem);

    float* wqkv_ptr;  cudaGetSymbolAddress((void**)&wqkv_ptr,  g_wqkv);
    float* wproj_ptr; cudaGetSymbolAddress((void**)&wproj_ptr, g_wproj);

    bias_pre_kernel<<<(NTOK * NTOK) / 32, 256>>>(table, pos);
    wperm_kernel<<<(9 * 24 * 8 * 8 * 4 + 255) / 256, 256>>>(qkv_w,  wqkv_ptr, 9);
    wperm_kernel<<<(3 * 24 * 8 * 8 * 4 + 255) / 256, 256>>>(proj_w, wproj_ptr, 3);
    qkv_kernel<<<NBW, 288, lin_smem>>>(x, qkv_b);
    attn_kernel<<<dim3(NH, NBW), 288, attn_smem>>>(mask);
    proj_kernel<<<NBW, 288, lin_smem>>>(proj_b, out);
}

// round 10
// speedup vs baseline: 2.3192x; 1.5196x over previous
#include <cuda_runtime.h>
#include <cstdint>

// ---------------- problem constants ----------------
#define B_LON 30
#define NW    32
#define NTOK  144
#define CDIM  192
#define NH    6
#define HD    32
#define NBW   (B_LON * NW)          // 960
#define SCALE 0.17677669529663687f  // 1/sqrt(32)

#define SXS 200   // x smem stride (K-permuted pairs), ≡8 mod 32 -> conflict-free LDS.64
#define QVS 40    // q/k smem stride (natural)
#define VTS 148   // v^T smem stride (d-major, m pair-permuted); ≡20 mod 32 -> conflict-free

// ---------------- scratch (device globals; no allocs allowed) ----------------
__device__ float g_q[NBW * NH * NTOK * HD];     // pre-scaled, tf32-rounded, [bw][h][n][d]
__device__ float g_k[NBW * NH * NTOK * HD];
__device__ float g_v[NBW * NH * NTOK * HD];
__device__ float g_o[NBW * NTOK * CDIM];        // attention output, [bw][n][c]
__device__ float g_bias[CDIM * NTOK * NTOK];    // dense bias, [(w*6+h)][n][m]
__device__ float g_wqkv[576 * CDIM];            // fragment-direct qkv weights (tf32)
__device__ float g_wproj[CDIM * CDIM];          // fragment-direct proj weights (tf32)

// ---------------- helpers ----------------
__device__ __forceinline__ uint32_t f2tf(float x) {
    uint32_t r; asm("cvt.rna.tf32.f32 %0, %1;" : "=r"(r) : "f"(x)); return r;
}
__device__ __forceinline__ float f2tff(float x) {
    return __uint_as_float(f2tf(x));
}
// V^T m-permutation: position p holds logical m' where p = (m'>>1) | ((m'&1)<<2).
__device__ __forceinline__ int vperm(int m) {
    return (m & ~7) | ((m & 7) >> 1) | ((m & 1) << 2);
}
__device__ __forceinline__ void mma_tf32(float c[4], uint32_t a0, uint32_t a1,
                                         uint32_t a2, uint32_t a3,
                                         uint32_t b0, uint32_t b1) {
    asm volatile(
        "mma.sync.aligned.m16n8k8.row.col.f32.tf32.tf32.f32 "
        "{%0,%1,%2,%3}, {%4,%5,%6,%7}, {%8,%9}, {%0,%1,%2,%3};\n"
        : "+f"(c[0]), "+f"(c[1]), "+f"(c[2]), "+f"(c[3])
        : "r"(a0), "r"(a1), "r"(a2), "r"(a3), "r"(b0), "r"(b1));
}

// ---------------- kernel 0a: densify earth-position bias ----------------
__global__ __launch_bounds__(256) void bias_pre_kernel(
    const float* __restrict__ table, const int* __restrict__ pos) {
    __shared__ float sm[CDIM * 33];
    __shared__ int sidx[32];
    int p0 = blockIdx.x * 32;
    int tid = threadIdx.x;
    if (tid < 32) sidx[tid] = pos[p0 + tid];
    __syncthreads();
    for (int i = tid; i < 32 * CDIM; i += 256) {
        int p = i / CDIM, whc = i % CDIM;
        sm[whc * 33 + p] = table[(long)sidx[p] * CDIM + whc];
    }
    __syncthreads();
    for (int i = tid; i < 32 * CDIM; i += 256) {
        int wh = i / 32, p = i % 32;
        g_bias[(long)wh * (NTOK * NTOK) + p0 + p] = sm[wh * 33 + p];
    }
}

// ---------------- kernel 0b: pre-permute weights into fragment-direct layout ----------
__global__ __launch_bounds__(256) void wperm_kernel(
    const float* __restrict__ wt, float* __restrict__ dst, int nct) {
    int idx = blockIdx.x * 256 + threadIdx.x;
    int total = nct * 24 * 8 * 8 * 4;
    if (idx >= total) return;
    int tg = idx & 3;
    int r  = idx >> 2;
    int gp = r & 7;  r >>= 3;
    int t  = r & 7;  r >>= 3;
    int kk = r % 24;
    int ct = r / 24;
    int col = ct * 64 + t * 8 + gp;
    int k   = kk * 8 + tg;
    dst[idx * 2]     = f2tff(wt[(long)col * CDIM + k]);
    dst[idx * 2 + 1] = f2tff(wt[(long)col * CDIM + k + 4]);
}

// ---------------- kernel 1: QKV projection (A from smem, B direct from L2) ----------
__global__ __launch_bounds__(288, 1) void qkv_kernel(
    const float* __restrict__ x, const float* __restrict__ bias) {
    extern __shared__ float sm[];
    float* sx = sm;                 // 144 x SXS, tf32-rounded, K-pair-permuted
    int bw = blockIdx.x;
    int tid = threadIdx.x;
    int warp = tid >> 5, lane = tid & 31, gp = lane >> 2, tg = lane & 3;
    int m0 = warp * 16;

    const float* xp = x + (long)bw * NTOK * CDIM;
    for (int i = tid; i < NTOK * CDIM / 4; i += 288) {
        int e = i * 4;
        int n = e / CDIM, k = e % CDIM;
        float4 v = *(const float4*)(xp + e);
        float* d = sx + n * SXS + (k & ~7) + ((k >> 2) & 1);
        d[0] = f2tff(v.x); d[2] = f2tff(v.y); d[4] = f2tff(v.z); d[6] = f2tff(v.w);
    }
    __syncthreads();

    const float2* wq = (const float2*)g_wqkv;
    for (int ct = 0; ct < 9; ++ct) {
        float acc[8][4];
#pragma unroll
        for (int t = 0; t < 8; t++)
#pragma unroll
            for (int j = 0; j < 4; j++) acc[t][j] = 0.f;
#pragma unroll 4
        for (int kk = 0; kk < 24; ++kk) {
            int k0 = kk * 8;
            float2 pa0 = *(const float2*)(sx + (m0 + gp) * SXS + k0 + 2 * tg);
            float2 pa1 = *(const float2*)(sx + (m0 + gp + 8) * SXS + k0 + 2 * tg);
            uint32_t a0 = __float_as_uint(pa0.x), a2 = __float_as_uint(pa0.y);
            uint32_t a1 = __float_as_uint(pa1.x), a3 = __float_as_uint(pa1.y);
            const float2* wb = wq + (ct * 24 + kk) * 256 + lane;
#pragma unroll
            for (int t = 0; t < 8; ++t) {
                float2 pb = __ldg(wb + t * 32);
                mma_tf32(acc[t], a0, a1, a2, a3,
                         __float_as_uint(pb.x), __float_as_uint(pb.y));
            }
        }
        int c0 = ct * 64;
#pragma unroll
        for (int t = 0; t < 8; ++t) {
#pragma unroll
            for (int cc = 0; cc < 2; ++cc) {
                int col = c0 + t * 8 + 2 * tg + cc;
                int s = col / CDIM, rem = col % CDIM;
                int h = rem / HD, d = rem & (HD - 1);
                float bb = bias[col];
                float mul = (s == 0) ? SCALE : 1.f;
                float* dst = (s == 0) ? g_q : (s == 1) ? g_k : g_v;
                float* base = dst + (long)(bw * NH + h) * NTOK * HD + d;
                base[(m0 + gp) * HD]     = f2tff((acc[t][cc]     + bb) * mul);
                base[(m0 + gp + 8) * HD] = f2tff((acc[t][2 + cc] + bb) * mul);
            }
        }
    }
}

// ---------------- kernel 2: fused attention, scores register-resident ----------------
__global__ __launch_bounds__(288, 2) void attn_kernel(const float* __restrict__ mask) {
    extern __shared__ float sm[];
    float* sq  = sm;                      // 144 x QVS
    float* sk  = sq + NTOK * QVS;         // 144 x QVS
    float* svt = sk + NTOK * QVS;         // 32 x VTS  (v^T, m pair-permuted)
    int h  = blockIdx.x;
    int bw = blockIdx.y;
    int w  = bw % NW;
    int tid = threadIdx.x;
    int warp = tid >> 5, lane = tid & 31, gp = lane >> 2, tg = lane & 3;
    int m0 = warp * 16;

    long base = (long)(bw * NH + h) * NTOK * HD;
    const float* qp = g_q + base;
    const float* kp = g_k + base;
    const float* vp = g_v + base;
    for (int i = tid; i < NTOK * HD / 4; i += 288) {
        int n = i >> 3, d0 = (i & 7) * 4;
        *(float4*)(sq + n * QVS + d0) = *(const float4*)(qp + n * HD + d0);
        *(float4*)(sk + n * QVS + d0) = *(const float4*)(kp + n * HD + d0);
        float4 vv = *(const float4*)(vp + n * HD + d0);
        int np = vperm(n);
        svt[(d0 + 0) * VTS + np] = vv.x;
        svt[(d0 + 1) * VTS + np] = vv.y;
        svt[(d0 + 2) * VTS + np] = vv.z;
        svt[(d0 + 3) * VTS + np] = vv.w;
    }
    __syncthreads();

    // ---- QK^T: full 16x144 per warp in registers ----
    float acc[18][4];
#pragma unroll
    for (int t = 0; t < 18; t++)
#pragma unroll
        for (int j = 0; j < 4; j++) acc[t][j] = 0.f;
#pragma unroll
    for (int kk = 0; kk < 4; ++kk) {
        int k = kk * 8;
        const float* ab = sq + (m0 + gp) * QVS + k + tg;
        uint32_t a0 = __float_as_uint(ab[0]);
        uint32_t a1 = __float_as_uint(ab[8 * QVS]);
        uint32_t a2 = __float_as_uint(ab[4]);
        uint32_t a3 = __float_as_uint(ab[8 * QVS + 4]);
#pragma unroll
        for (int t = 0; t < 18; ++t) {
            const float* bb = sk + (t * 8 + gp) * QVS + k + tg;
            mma_tf32(acc[t], a0, a1, a2, a3,
                     __float_as_uint(bb[0]), __float_as_uint(bb[4]));
        }
    }

    // ---- bias + mask in registers ----
    const float* bp = g_bias + (long)(w * NH + h) * NTOK * NTOK;
    const float* mp = mask + (long)bw * NTOK * NTOK;
    int r0 = m0 + gp, r1 = r0 + 8;
#pragma unroll
    for (int t = 0; t < 18; ++t) {
        int mcol = t * 8 + 2 * tg;
        acc[t][0] += bp[r0 * NTOK + mcol]     + mp[r0 * NTOK + mcol];
        acc[t][1] += bp[r0 * NTOK + mcol + 1] + mp[r0 * NTOK + mcol + 1];
        acc[t][2] += bp[r1 * NTOK + mcol]     + mp[r1 * NTOK + mcol];
        acc[t][3] += bp[r1 * NTOK + mcol + 1] + mp[r1 * NTOK + mcol + 1];
    }

    // ---- softmax in registers (rows r0: slots 0,1 ; r1: slots 2,3) ----
    float mx0 = -1e30f, mx1 = -1e30f;
#pragma unroll
    for (int t = 0; t < 18; ++t) {
        mx0 = fmaxf(mx0, fmaxf(acc[t][0], acc[t][1]));
        mx1 = fmaxf(mx1, fmaxf(acc[t][2], acc[t][3]));
    }
    mx0 = fmaxf(mx0, __shfl_xor_sync(0xffffffffu, mx0, 1));
    mx0 = fmaxf(mx0, __shfl_xor_sync(0xffffffffu, mx0, 2));
    mx1 = fmaxf(mx1, __shfl_xor_sync(0xffffffffu, mx1, 1));
    mx1 = fmaxf(mx1, __shfl_xor_sync(0xffffffffu, mx1, 2));
    float s0 = 0.f, s1 = 0.f;
#pragma unroll
    for (int t = 0; t < 18; ++t) {
        acc[t][0] = __expf(acc[t][0] - mx0); s0 += acc[t][0];
        acc[t][1] = __expf(acc[t][1] - mx0); s0 += acc[t][1];
        acc[t][2] = __expf(acc[t][2] - mx1); s1 += acc[t][2];
        acc[t][3] = __expf(acc[t][3] - mx1); s1 += acc[t][3];
    }
    s0 += __shfl_xor_sync(0xffffffffu, s0, 1);
    s0 += __shfl_xor_sync(0xffffffffu, s0, 2);
    s1 += __shfl_xor_sync(0xffffffffu, s1, 1);
    s1 += __shfl_xor_sync(0xffffffffu, s1, 2);
    float inv0 = 1.f / s0, inv1 = 1.f / s1;
#pragma unroll
    for (int t = 0; t < 18; ++t) {
        acc[t][0] = f2tff(acc[t][0] * inv0);
        acc[t][1] = f2tff(acc[t][1] * inv0);
        acc[t][2] = f2tff(acc[t][2] * inv1);
        acc[t][3] = f2tff(acc[t][3] * inv1);
    }

    // ---- P @ V: A fragments straight from acc (C-layout == A-layout under vperm) ----
    float acc2[4][4];
#pragma unroll
    for (int t = 0; t < 4; t++)
#pragma unroll
        for (int j = 0; j < 4; j++) acc2[t][j] = 0.f;
#pragma unroll
    for (int t = 0; t < 18; ++t) {
        uint32_t a0 = __float_as_uint(acc[t][0]);   // row gp,   k=tg   (logical m=2tg)
        uint32_t a1 = __float_as_uint(acc[t][2]);   // row gp+8, k=tg
        uint32_t a2 = __float_as_uint(acc[t][1]);   // row gp,   k=tg+4 (logical m=2tg+1)
        uint32_t a3 = __float_as_uint(acc[t][3]);   // row gp+8, k=tg+4
        int k0 = t * 8;
#pragma unroll
        for (int nt = 0; nt < 4; ++nt) {
            const float* bb = svt + (nt * 8 + gp) * VTS + k0 + tg;
            mma_tf32(acc2[nt], a0, a1, a2, a3,
                     __float_as_uint(bb[0]), __float_as_uint(bb[4]));
        }
    }
    float* op = g_o + (long)bw * NTOK * CDIM + h * HD;
#pragma unroll
    for (int nt = 0; nt < 4; ++nt) {
        int d = nt * 8 + 2 * tg;
        op[r0 * CDIM + d]     = acc2[nt][0];
        op[r0 * CDIM + d + 1] = acc2[nt][1];
        op[r1 * CDIM + d]     = acc2[nt][2];
        op[r1 * CDIM + d + 1] = acc2[nt][3];
    }
}

// ---------------- kernel 3: output projection (A from smem, B direct from L2) ------
__global__ __launch_bounds__(288, 1) void proj_kernel(
    const float* __restrict__ bias, float* __restrict__ out) {
    extern __shared__ float sm[];
    float* sx = sm;                 // 144 x SXS
    int bw = blockIdx.x;
    int tid = threadIdx.x;
    int warp = tid >> 5, lane = tid & 31, gp = lane >> 2, tg = lane & 3;
    int m0 = warp * 16;

    const float* xp = g_o + (long)bw * NTOK * CDIM;
    for (int i = tid; i < NTOK * CDIM / 4; i += 288) {
        int e = i * 4;
        int n = e / CDIM, k = e % CDIM;
        float4 v = *(const float4*)(xp + e);
        float* d = sx + n * SXS + (k & ~7) + ((k >> 2) & 1);
        d[0] = f2tff(v.x); d[2] = f2tff(v.y); d[4] = f2tff(v.z); d[6] = f2tff(v.w);
    }
    __syncthreads();

    const float2* wp = (const float2*)g_wproj;
    for (int ct = 0; ct < 3; ++ct) {
        float acc[8][4];
#pragma unroll
        for (int t = 0; t < 8; t++)
#pragma unroll
            for (int j = 0; j < 4; j++) acc[t][j] = 0.f;
#pragma unroll 4
        for (int kk = 0; kk < 24; ++kk) {
            int k0 = kk * 8;
            float2 pa0 = *(const float2*)(sx + (m0 + gp) * SXS + k0 + 2 * tg);
            float2 pa1 = *(const float2*)(sx + (m0 + gp + 8) * SXS + k0 + 2 * tg);
            uint32_t a0 = __float_as_uint(pa0.x), a2 = __float_as_uint(pa0.y);
            uint32_t a1 = __float_as_uint(pa1.x), a3 = __float_as_uint(pa1.y);
            const float2* wb = wp + (ct * 24 + kk) * 256 + lane;
#pragma unroll
            for (int t = 0; t < 8; ++t) {
                float2 pb = __ldg(wb + t * 32);
                mma_tf32(acc[t], a0, a1, a2, a3,
                         __float_as_uint(pb.x), __float_as_uint(pb.y));
            }
        }
        int c0 = ct * 64;
        float* ob = out + (long)bw * NTOK * CDIM;
#pragma unroll
        for (int t = 0; t < 8; ++t) {
#pragma unroll
            for (int cc = 0; cc < 2; ++cc) {
                int col = c0 + t * 8 + 2 * tg + cc;
                float bb = bias[col];
                ob[(m0 + gp) * CDIM + col]     = acc[t][cc]     + bb;
                ob[(m0 + gp + 8) * CDIM + col] = acc[t][2 + cc] + bb;
            }
        }
    }
}

// ---------------- launch ----------------
extern "C" void kernel_launch(void* const* d_in, const int* in_sizes, int n_in,
                              void* d_out, int out_size) {
    const float* x      = (const float*)d_in[0];
    const float* mask   = (const float*)d_in[1];
    const float* qkv_w  = (const float*)d_in[2];
    const float* qkv_b  = (const float*)d_in[3];
    const float* proj_w = (const float*)d_in[4];
    const float* proj_b = (const float*)d_in[5];
    const float* table  = (const float*)d_in[6];
    const int*   pos    = (const int*)d_in[7];
    float* out = (float*)d_out;

    const int lin_smem  = NTOK * SXS * 4;                          // 115200 B
    const int attn_smem = (2 * NTOK * QVS + HD * VTS) * 4;         // 65024 B
    cudaFuncSetAttribute(qkv_kernel,  cudaFuncAttributeMaxDynamicSharedMemorySize, lin_smem);
    cudaFuncSetAttribute(proj_kernel, cudaFuncAttributeMaxDynamicSharedMemorySize, lin_smem);
    cudaFuncSetAttribute(attn_kernel, cudaFuncAttributeMaxDynamicSharedMemorySize, attn_smem);

    float* wqkv_ptr;  cudaGetSymbolAddress((void**)&wqkv_ptr,  g_wqkv);
    float* wproj_ptr; cudaGetSymbolAddress((void**)&wproj_ptr, g_wproj);

    bias_pre_kernel<<<(NTOK * NTOK) / 32, 256>>>(table, pos);
    wperm_kernel<<<(9 * 24 * 8 * 8 * 4 + 255) / 256, 256>>>(qkv_w,  wqkv_ptr, 9);
    wperm_kernel<<<(3 * 24 * 8 * 8 * 4 + 255) / 256, 256>>>(proj_w, wproj_ptr, 3);
    qkv_kernel<<<NBW, 288, lin_smem>>>(x, qkv_b);
    attn_kernel<<<dim3(NH, NBW), 288, attn_smem>>>(mask);
    proj_kernel<<<NBW, 288, lin_smem>>>(proj_b, out);
}

// round 11
// speedup vs baseline: 2.5405x; 1.0954x over previous
#include <cuda_runtime.h>
#include <cstdint>

// ---------------- problem constants ----------------
#define B_LON 30
#define NW    32
#define NTOK  144
#define CDIM  192
#define NH    6
#define HD    32
#define NBW   (B_LON * NW)          // 960
#define SCALE 0.17677669529663687f  // 1/sqrt(32)

#define SXS 200   // x smem stride (K-permuted pairs), ≡8 mod 32 -> conflict-free LDS.64
#define QVS 40    // q/k smem stride (natural)
#define VTS 148   // v^T smem stride (d-major, m pair-permuted); ≡20 mod 32 -> conflict-free

// ---------------- scratch (device globals; no allocs allowed) ----------------
__device__ float g_q[NBW * NH * NTOK * HD];     // pre-scaled, tf32-rounded, [bw][h][n][d]
__device__ float g_k[NBW * NH * NTOK * HD];
__device__ float g_v[NBW * NH * NTOK * HD];
__device__ float g_o[NBW * NTOK * CDIM];        // attention output, [bw][n][c]
__device__ float g_bias[CDIM * NTOK * NTOK];    // dense bias, [(w*6+h)][n][m]
__device__ float g_wqkv[576 * CDIM];            // fragment-direct qkv weights (tf32)
__device__ float g_wproj[CDIM * CDIM];          // fragment-direct proj weights (tf32)

// ---------------- helpers ----------------
__device__ __forceinline__ uint32_t f2tf(float x) {
    uint32_t r; asm("cvt.rna.tf32.f32 %0, %1;" : "=r"(r) : "f"(x)); return r;
}
__device__ __forceinline__ float f2tff(float x) {
    return __uint_as_float(f2tf(x));
}
// V^T m-permutation: position p holds logical m' where p = (m'>>1) | ((m'&1)<<2).
__device__ __forceinline__ int vperm(int m) {
    return (m & ~7) | ((m & 7) >> 1) | ((m & 1) << 2);
}
__device__ __forceinline__ void mma_tf32(float c[4], uint32_t a0, uint32_t a1,
                                         uint32_t a2, uint32_t a3,
                                         uint32_t b0, uint32_t b1) {
    asm volatile(
        "mma.sync.aligned.m16n8k8.row.col.f32.tf32.tf32.f32 "
        "{%0,%1,%2,%3}, {%4,%5,%6,%7}, {%8,%9}, {%0,%1,%2,%3};\n"
        : "+f"(c[0]), "+f"(c[1]), "+f"(c[2]), "+f"(c[3])
        : "r"(a0), "r"(a1), "r"(a2), "r"(a3), "r"(b0), "r"(b1));
}

// ---------------- kernel 0a: densify earth-position bias ----------------
__global__ __launch_bounds__(256) void bias_pre_kernel(
    const float* __restrict__ table, const int* __restrict__ pos) {
    __shared__ float sm[CDIM * 33];
    __shared__ int sidx[32];
    int p0 = blockIdx.x * 32;
    int tid = threadIdx.x;
    if (tid < 32) sidx[tid] = pos[p0 + tid];
    __syncthreads();
    for (int i = tid; i < 32 * CDIM; i += 256) {
        int p = i / CDIM, whc = i % CDIM;
        sm[whc * 33 + p] = table[(long)sidx[p] * CDIM + whc];
    }
    __syncthreads();
    for (int i = tid; i < 32 * CDIM; i += 256) {
        int wh = i / 32, p = i % 32;
        g_bias[(long)wh * (NTOK * NTOK) + p0 + p] = sm[wh * 33 + p];
    }
}

// ---------------- kernel 0b: pre-permute weights into fragment-direct layout ----------
__global__ __launch_bounds__(256) void wperm_kernel(
    const float* __restrict__ wt, float* __restrict__ dst, int nct) {
    int idx = blockIdx.x * 256 + threadIdx.x;
    int total = nct * 24 * 8 * 8 * 4;
    if (idx >= total) return;
    int tg = idx & 3;
    int r  = idx >> 2;
    int gp = r & 7;  r >>= 3;
    int t  = r & 7;  r >>= 3;
    int kk = r % 24;
    int ct = r / 24;
    int col = ct * 64 + t * 8 + gp;
    int k   = kk * 8 + tg;
    dst[idx * 2]     = f2tff(wt[(long)col * CDIM + k]);
    dst[idx * 2 + 1] = f2tff(wt[(long)col * CDIM + k + 4]);
}

// ---------------- kernel 1: QKV projection (A from smem, B direct from L2) ----------
// 2 CTAs/SM: regs capped at 112, smem 115200*2+reserve fits 228KB/SM.
__global__ __launch_bounds__(288, 2) void qkv_kernel(
    const float* __restrict__ x, const float* __restrict__ bias) {
    extern __shared__ float sm[];
    float* sx = sm;                 // 144 x SXS, tf32-rounded, K-pair-permuted
    int bw = blockIdx.x;
    int tid = threadIdx.x;
    int warp = tid >> 5, lane = tid & 31, gp = lane >> 2, tg = lane & 3;
    int m0 = warp * 16;

    const float* xp = x + (long)bw * NTOK * CDIM;
    for (int i = tid; i < NTOK * CDIM / 4; i += 288) {
        int e = i * 4;
        int n = e / CDIM, k = e % CDIM;
        float4 v = *(const float4*)(xp + e);
        float* d = sx + n * SXS + (k & ~7) + ((k >> 2) & 1);
        d[0] = f2tff(v.x); d[2] = f2tff(v.y); d[4] = f2tff(v.z); d[6] = f2tff(v.w);
    }
    __syncthreads();

    const float2* wq = (const float2*)g_wqkv;
    for (int ct = 0; ct < 9; ++ct) {
        float acc[8][4];
#pragma unroll
        for (int t = 0; t < 8; t++)
#pragma unroll
            for (int j = 0; j < 4; j++) acc[t][j] = 0.f;
#pragma unroll 2
        for (int kk = 0; kk < 24; ++kk) {
            int k0 = kk * 8;
            float2 pa0 = *(const float2*)(sx + (m0 + gp) * SXS + k0 + 2 * tg);
            float2 pa1 = *(const float2*)(sx + (m0 + gp + 8) * SXS + k0 + 2 * tg);
            uint32_t a0 = __float_as_uint(pa0.x), a2 = __float_as_uint(pa0.y);
            uint32_t a1 = __float_as_uint(pa1.x), a3 = __float_as_uint(pa1.y);
            const float2* wb = wq + (ct * 24 + kk) * 256 + lane;
#pragma unroll
            for (int t = 0; t < 8; ++t) {
                float2 pb = __ldg(wb + t * 32);
                mma_tf32(acc[t], a0, a1, a2, a3,
                         __float_as_uint(pb.x), __float_as_uint(pb.y));
            }
        }
        int c0 = ct * 64;
#pragma unroll
        for (int t = 0; t < 8; ++t) {
#pragma unroll
            for (int cc = 0; cc < 2; ++cc) {
                int col = c0 + t * 8 + 2 * tg + cc;
                int s = col / CDIM, rem = col % CDIM;
                int h = rem / HD, d = rem & (HD - 1);
                float bb = bias[col];
                float mul = (s == 0) ? SCALE : 1.f;
                float* dst = (s == 0) ? g_q : (s == 1) ? g_k : g_v;
                float* base = dst + (long)(bw * NH + h) * NTOK * HD + d;
                base[(m0 + gp) * HD]     = f2tff((acc[t][cc]     + bb) * mul);
                base[(m0 + gp + 8) * HD] = f2tff((acc[t][2 + cc] + bb) * mul);
            }
        }
    }
}

// ---------------- kernel 2: fused attention, scores register-resident ----------------
__global__ __launch_bounds__(288, 2) void attn_kernel(const float* __restrict__ mask) {
    extern __shared__ float sm[];
    float* sq  = sm;                      // 144 x QVS
    float* sk  = sq + NTOK * QVS;         // 144 x QVS
    float* svt = sk + NTOK * QVS;         // 32 x VTS  (v^T, m pair-permuted)
    int h  = blockIdx.x;
    int bw = blockIdx.y;
    int w  = bw % NW;
    int tid = threadIdx.x;
    int warp = tid >> 5, lane = tid & 31, gp = lane >> 2, tg = lane & 3;
    int m0 = warp * 16;

    long base = (long)(bw * NH + h) * NTOK * HD;
    const float* qp = g_q + base;
    const float* kp = g_k + base;
    const float* vp = g_v + base;
    for (int i = tid; i < NTOK * HD / 4; i += 288) {
        int n = i >> 3, d0 = (i & 7) * 4;
        *(float4*)(sq + n * QVS + d0) = *(const float4*)(qp + n * HD + d0);
        *(float4*)(sk + n * QVS + d0) = *(const float4*)(kp + n * HD + d0);
        float4 vv = *(const float4*)(vp + n * HD + d0);
        int np = vperm(n);
        svt[(d0 + 0) * VTS + np] = vv.x;
        svt[(d0 + 1) * VTS + np] = vv.y;
        svt[(d0 + 2) * VTS + np] = vv.z;
        svt[(d0 + 3) * VTS + np] = vv.w;
    }
    __syncthreads();

    // ---- QK^T: full 16x144 per warp in registers ----
    float acc[18][4];
#pragma unroll
    for (int t = 0; t < 18; t++)
#pragma unroll
        for (int j = 0; j < 4; j++) acc[t][j] = 0.f;
#pragma unroll
    for (int kk = 0; kk < 4; ++kk) {
        int k = kk * 8;
        const float* ab = sq + (m0 + gp) * QVS + k + tg;
        uint32_t a0 = __float_as_uint(ab[0]);
        uint32_t a1 = __float_as_uint(ab[8 * QVS]);
        uint32_t a2 = __float_as_uint(ab[4]);
        uint32_t a3 = __float_as_uint(ab[8 * QVS + 4]);
#pragma unroll
        for (int t = 0; t < 18; ++t) {
            const float* bb = sk + (t * 8 + gp) * QVS + k + tg;
            mma_tf32(acc[t], a0, a1, a2, a3,
                     __float_as_uint(bb[0]), __float_as_uint(bb[4]));
        }
    }

    // ---- bias + mask in registers (vectorized float2 loads) ----
    const float* bp = g_bias + (long)(w * NH + h) * NTOK * NTOK;
    const float* mp = mask + (long)bw * NTOK * NTOK;
    int r0 = m0 + gp, r1 = r0 + 8;
#pragma unroll
    for (int t = 0; t < 18; ++t) {
        int mcol = t * 8 + 2 * tg;
        float2 b0 = __ldg((const float2*)(bp + r0 * NTOK + mcol));
        float2 b1 = __ldg((const float2*)(bp + r1 * NTOK + mcol));
        float2 q0 = __ldg((const float2*)(mp + r0 * NTOK + mcol));
        float2 q1 = __ldg((const float2*)(mp + r1 * NTOK + mcol));
        acc[t][0] += b0.x + q0.x;
        acc[t][1] += b0.y + q0.y;
        acc[t][2] += b1.x + q1.x;
        acc[t][3] += b1.y + q1.y;
    }

    // ---- softmax in registers (rows r0: slots 0,1 ; r1: slots 2,3) ----
    float mx0 = -1e30f, mx1 = -1e30f;
#pragma unroll
    for (int t = 0; t < 18; ++t) {
        mx0 = fmaxf(mx0, fmaxf(acc[t][0], acc[t][1]));
        mx1 = fmaxf(mx1, fmaxf(acc[t][2], acc[t][3]));
    }
    mx0 = fmaxf(mx0, __shfl_xor_sync(0xffffffffu, mx0, 1));
    mx0 = fmaxf(mx0, __shfl_xor_sync(0xffffffffu, mx0, 2));
    mx1 = fmaxf(mx1, __shfl_xor_sync(0xffffffffu, mx1, 1));
    mx1 = fmaxf(mx1, __shfl_xor_sync(0xffffffffu, mx1, 2));
    float s0 = 0.f, s1 = 0.f;
#pragma unroll
    for (int t = 0; t < 18; ++t) {
        acc[t][0] = __expf(acc[t][0] - mx0); s0 += acc[t][0];
        acc[t][1] = __expf(acc[t][1] - mx0); s0 += acc[t][1];
        acc[t][2] = __expf(acc[t][2] - mx1); s1 += acc[t][2];
        acc[t][3] = __expf(acc[t][3] - mx1); s1 += acc[t][3];
    }
    s0 += __shfl_xor_sync(0xffffffffu, s0, 1);
    s0 += __shfl_xor_sync(0xffffffffu, s0, 2);
    s1 += __shfl_xor_sync(0xffffffffu, s1, 1);
    s1 += __shfl_xor_sync(0xffffffffu, s1, 2);
    float inv0 = 1.f / s0, inv1 = 1.f / s1;
#pragma unroll
    for (int t = 0; t < 18; ++t) {
        acc[t][0] = f2tff(acc[t][0] * inv0);
        acc[t][1] = f2tff(acc[t][1] * inv0);
        acc[t][2] = f2tff(acc[t][2] * inv1);
        acc[t][3] = f2tff(acc[t][3] * inv1);
    }

    // ---- P @ V: A fragments straight from acc (C-layout == A-layout under vperm) ----
    float acc2[4][4];
#pragma unroll
    for (int t = 0; t < 4; t++)
#pragma unroll
        for (int j = 0; j < 4; j++) acc2[t][j] = 0.f;
#pragma unroll
    for (int t = 0; t < 18; ++t) {
        uint32_t a0 = __float_as_uint(acc[t][0]);
        uint32_t a1 = __float_as_uint(acc[t][2]);
        uint32_t a2 = __float_as_uint(acc[t][1]);
        uint32_t a3 = __float_as_uint(acc[t][3]);
        int k0 = t * 8;
#pragma unroll
        for (int nt = 0; nt < 4; ++nt) {
            const float* bb = svt + (nt * 8 + gp) * VTS + k0 + tg;
            mma_tf32(acc2[nt], a0, a1, a2, a3,
                     __float_as_uint(bb[0]), __float_as_uint(bb[4]));
        }
    }
    float* op = g_o + (long)bw * NTOK * CDIM + h * HD;
#pragma unroll
    for (int nt = 0; nt < 4; ++nt) {
        int d = nt * 8 + 2 * tg;
        op[r0 * CDIM + d]     = acc2[nt][0];
        op[r0 * CDIM + d + 1] = acc2[nt][1];
        op[r1 * CDIM + d]     = acc2[nt][2];
        op[r1 * CDIM + d + 1] = acc2[nt][3];
    }
}

// ---------------- kernel 3: output projection (A from smem, B direct from L2) ------
__global__ __launch_bounds__(288, 2) void proj_kernel(
    const float* __restrict__ bias, float* __restrict__ out) {
    extern __shared__ float sm[];
    float* sx = sm;                 // 144 x SXS
    int bw = blockIdx.x;
    int tid = threadIdx.x;
    int warp = tid >> 5, lane = tid & 31, gp = lane >> 2, tg = lane & 3;
    int m0 = warp * 16;

    const float* xp = g_o + (long)bw * NTOK * CDIM;
    for (int i = tid; i < NTOK * CDIM / 4; i += 288) {
        int e = i * 4;
        int n = e / CDIM, k = e % CDIM;
        float4 v = *(const float4*)(xp + e);
        float* d = sx + n * SXS + (k & ~7) + ((k >> 2) & 1);
        d[0] = f2tff(v.x); d[2] = f2tff(v.y); d[4] = f2tff(v.z); d[6] = f2tff(v.w);
    }
    __syncthreads();

    const float2* wp = (const float2*)g_wproj;
    for (int ct = 0; ct < 3; ++ct) {
        float acc[8][4];
#pragma unroll
        for (int t = 0; t < 8; t++)
#pragma unroll
            for (int j = 0; j < 4; j++) acc[t][j] = 0.f;
#pragma unroll 2
        for (int kk = 0; kk < 24; ++kk) {
            int k0 = kk * 8;
            float2 pa0 = *(const float2*)(sx + (m0 + gp) * SXS + k0 + 2 * tg);
            float2 pa1 = *(const float2*)(sx + (m0 + gp + 8) * SXS + k0 + 2 * tg);
            uint32_t a0 = __float_as_uint(pa0.x), a2 = __float_as_uint(pa0.y);
            uint32_t a1 = __float_as_uint(pa1.x), a3 = __float_as_uint(pa1.y);
            const float2* wb = wp + (ct * 24 + kk) * 256 + lane;
#pragma unroll
            for (int t = 0; t < 8; ++t) {
                float2 pb = __ldg(wb + t * 32);
                mma_tf32(acc[t], a0, a1, a2, a3,
                         __float_as_uint(pb.x), __float_as_uint(pb.y));
            }
        }
        int c0 = ct * 64;
        float* ob = out + (long)bw * NTOK * CDIM;
#pragma unroll
        for (int t = 0; t < 8; ++t) {
#pragma unroll
            for (int cc = 0; cc < 2; ++cc) {
                int col = c0 + t * 8 + 2 * tg + cc;
                float bb = bias[col];
                ob[(m0 + gp) * CDIM + col]     = acc[t][cc]     + bb;
                ob[(m0 + gp + 8) * CDIM + col] = acc[t][2 + cc] + bb;
            }
        }
    }
}

// ---------------- launch ----------------
extern "C" void kernel_launch(void* const* d_in, const int* in_sizes, int n_in,
                              void* d_out, int out_size) {
    const float* x      = (const float*)d_in[0];
    const float* mask   = (const float*)d_in[1];
    const float* qkv_w  = (const float*)d_in[2];
    const float* qkv_b  = (const float*)d_in[3];
    const float* proj_w = (const float*)d_in[4];
    const float* proj_b = (const float*)d_in[5];
    const float* table  = (const float*)d_in[6];
    const int*   pos    = (const int*)d_in[7];
    float* out = (float*)d_out;

    const int lin_smem  = NTOK * SXS * 4;                          // 115200 B
    const int attn_smem = (2 * NTOK * QVS + HD * VTS) * 4;         // 65024 B
    cudaFuncSetAttribute(qkv_kernel,  cudaFuncAttributeMaxDynamicSharedMemorySize, lin_smem);
    cudaFuncSetAttribute(proj_kernel, cudaFuncAttributeMaxDynamicSharedMemorySize, lin_smem);
    cudaFuncSetAttribute(attn_kernel, cudaFuncAttributeMaxDynamicSharedMemorySize, attn_smem);

    float* wqkv_ptr;  cudaGetSymbolAddress((void**)&wqkv_ptr,  g_wqkv);
    float* wproj_ptr; cudaGetSymbolAddress((void**)&wproj_ptr, g_wproj);

    bias_pre_kernel<<<(NTOK * NTOK) / 32, 256>>>(table, pos);
    wperm_kernel<<<(9 * 24 * 8 * 8 * 4 + 255) / 256, 256>>>(qkv_w,  wqkv_ptr, 9);
    wperm_kernel<<<(3 * 24 * 8 * 8 * 4 + 255) / 256, 256>>>(proj_w, wproj_ptr, 3);
    qkv_kernel<<<NBW, 288, lin_smem>>>(x, qkv_b);
    attn_kernel<<<dim3(NH, NBW), 288, attn_smem>>>(mask);
    proj_kernel<<<NBW, 288, lin_smem>>>(proj_b, out);
}

// round 17
// speedup vs baseline: 3.0590x; 1.2041x over previous
#include <cuda_runtime.h>
#include <cstdint>

// ---------------- problem constants ----------------
#define B_LON 30
#define NW    32
#define NTOK  144
#define CDIM  192
#define NH    6
#define HD    32
#define NBW   (B_LON * NW)          // 960
#define SCALE 0.17677669529663687f  // 1/sqrt(32)

#define SXS 200   // x smem stride (K-permuted pairs), ≡8 mod 32 -> conflict-free LDS.64
#define QVS 40    // q/k smem stride (natural)
#define VTS 148   // v^T smem stride (d-major, m pair-permuted); ≡20 mod 32 -> conflict-free

// ---------------- scratch (device globals; no allocs allowed) ----------------
__device__ float g_q[NBW * NH * NTOK * HD];     // pre-scaled, tf32-rounded, [bw][h][n][d]
__device__ float g_k[NBW * NH * NTOK * HD];
__device__ float g_v[NBW * NH * NTOK * HD];
// attention output, fragment-direct: float2[bw][kk=24][n=144][tg=4] = {o[n][8kk+tg], o[n][8kk+tg+4]}
__device__ float g_o2[NBW * 24 * NTOK * 4 * 2];
__device__ float g_bias[CDIM * NTOK * NTOK];    // dense bias, [(w*6+h)][n][m]
__device__ float g_wqkv[576 * CDIM];            // fragment-direct qkv weights (tf32)
__device__ float g_wproj[CDIM * CDIM];          // fragment-direct proj weights (tf32)

// ---------------- helpers ----------------
__device__ __forceinline__ uint32_t f2tf(float x) {
    uint32_t r; asm("cvt.rna.tf32.f32 %0, %1;" : "=r"(r) : "f"(x)); return r;
}
__device__ __forceinline__ float f2tff(float x) {
    return __uint_as_float(f2tf(x));
}
// V^T m-permutation: position p holds logical m' where p = (m'>>1) | ((m'&1)<<2).
__device__ __forceinline__ int vperm(int m) {
    return (m & ~7) | ((m & 7) >> 1) | ((m & 1) << 2);
}
__device__ __forceinline__ void mma_tf32(float c[4], uint32_t a0, uint32_t a1,
                                         uint32_t a2, uint32_t a3,
                                         uint32_t b0, uint32_t b1) {
    asm volatile(
        "mma.sync.aligned.m16n8k8.row.col.f32.tf32.tf32.f32 "
        "{%0,%1,%2,%3}, {%4,%5,%6,%7}, {%8,%9}, {%0,%1,%2,%3};\n"
        : "+f"(c[0]), "+f"(c[1]), "+f"(c[2]), "+f"(c[3])
        : "r"(a0), "r"(a1), "r"(a2), "r"(a3), "r"(b0), "r"(b1));
}

// ---------------- kernel 0a: densify earth-position bias ----------------
__global__ __launch_bounds__(256) void bias_pre_kernel(
    const float* __restrict__ table, const int* __restrict__ pos) {
    __shared__ float sm[CDIM * 33];
    __shared__ int sidx[32];
    int p0 = blockIdx.x * 32;
    int tid = threadIdx.x;
    if (tid < 32) sidx[tid] = pos[p0 + tid];
    __syncthreads();
    for (int i = tid; i < 32 * CDIM; i += 256) {
        int p = i / CDIM, whc = i % CDIM;
        sm[whc * 33 + p] = table[(long)sidx[p] * CDIM + whc];
    }
    __syncthreads();
    for (int i = tid; i < 32 * CDIM; i += 256) {
        int wh = i / 32, p = i % 32;
        g_bias[(long)wh * (NTOK * NTOK) + p0 + p] = sm[wh * 33 + p];
    }
}

// ---------------- kernel 0b: pre-permute weights into fragment-direct layout ----------
__global__ __launch_bounds__(256) void wperm_kernel(
    const float* __restrict__ wt, float* __restrict__ dst, int nct) {
    int idx = blockIdx.x * 256 + threadIdx.x;
    int total = nct * 24 * 8 * 8 * 4;
    if (idx >= total) return;
    int tg = idx & 3;
    int r  = idx >> 2;
    int gp = r & 7;  r >>= 3;
    int t  = r & 7;  r >>= 3;
    int kk = r % 24;
    int ct = r / 24;
    int col = ct * 64 + t * 8 + gp;
    int k   = kk * 8 + tg;
    dst[idx * 2]     = f2tff(wt[(long)col * CDIM + k]);
    dst[idx * 2 + 1] = f2tff(wt[(long)col * CDIM + k + 4]);
}

// ---------------- kernel 1: QKV projection (A from smem, B direct from L2) ----------
__global__ __launch_bounds__(288, 2) void qkv_kernel(
    const float* __restrict__ x, const float* __restrict__ bias) {
    extern __shared__ float sm[];
    float* sx = sm;                 // 144 x SXS, tf32-rounded, K-pair-permuted
    int bw = blockIdx.x;
    int tid = threadIdx.x;
    int warp = tid >> 5, lane = tid & 31, gp = lane >> 2, tg = lane & 3;
    int m0 = warp * 16;

    const float* xp = x + (long)bw * NTOK * CDIM;
    for (int i = tid; i < NTOK * CDIM / 4; i += 288) {
        int e = i * 4;
        int n = e / CDIM, k = e % CDIM;
        float4 v = *(const float4*)(xp + e);
        float* d = sx + n * SXS + (k & ~7) + ((k >> 2) & 1);
        d[0] = f2tff(v.x); d[2] = f2tff(v.y); d[4] = f2tff(v.z); d[6] = f2tff(v.w);
    }
    __syncthreads();

    const float2* wq = (const float2*)g_wqkv;
    for (int ct = 0; ct < 9; ++ct) {
        float acc[8][4];
#pragma unroll
        for (int t = 0; t < 8; t++)
#pragma unroll
            for (int j = 0; j < 4; j++) acc[t][j] = 0.f;
#pragma unroll 2
        for (int kk = 0; kk < 24; ++kk) {
            int k0 = kk * 8;
            float2 pa0 = *(const float2*)(sx + (m0 + gp) * SXS + k0 + 2 * tg);
            float2 pa1 = *(const float2*)(sx + (m0 + gp + 8) * SXS + k0 + 2 * tg);
            uint32_t a0 = __float_as_uint(pa0.x), a2 = __float_as_uint(pa0.y);
            uint32_t a1 = __float_as_uint(pa1.x), a3 = __float_as_uint(pa1.y);
            const float2* wb = wq + (ct * 24 + kk) * 256 + lane;
#pragma unroll
            for (int t = 0; t < 8; ++t) {
                float2 pb = __ldg(wb + t * 32);
                mma_tf32(acc[t], a0, a1, a2, a3,
                         __float_as_uint(pb.x), __float_as_uint(pb.y));
            }
        }
        int c0 = ct * 64;
#pragma unroll
        for (int t = 0; t < 8; ++t) {
#pragma unroll
            for (int cc = 0; cc < 2; ++cc) {
                int col = c0 + t * 8 + 2 * tg + cc;
                int s = col / CDIM, rem = col % CDIM;
                int h = rem / HD, d = rem & (HD - 1);
                float bb = bias[col];
                float mul = (s == 0) ? SCALE : 1.f;
                float* dst = (s == 0) ? g_q : (s == 1) ? g_k : g_v;
                float* base = dst + (long)(bw * NH + h) * NTOK * HD + d;
                base[(m0 + gp) * HD]     = f2tff((acc[t][cc]     + bb) * mul);
                base[(m0 + gp + 8) * HD] = f2tff((acc[t][2 + cc] + bb) * mul);
            }
        }
    }
}

// ---------------- kernel 2: fused attention, scores register-resident ----------------
__global__ __launch_bounds__(288, 2) void attn_kernel(const float* __restrict__ mask) {
    extern __shared__ float sm[];
    float* sq  = sm;                      // 144 x QVS
    float* sk  = sq + NTOK * QVS;         // 144 x QVS
    float* svt = sk + NTOK * QVS;         // 32 x VTS  (v^T, m pair-permuted)
    int h  = blockIdx.x;
    int bw = blockIdx.y;
    int w  = bw % NW;
    int tid = threadIdx.x;
    int warp = tid >> 5, lane = tid & 31, gp = lane >> 2, tg = lane & 3;
    int m0 = warp * 16;

    long base = (long)(bw * NH + h) * NTOK * HD;
    const float* qp = g_q + base;
    const float* kp = g_k + base;
    const float* vp = g_v + base;
    for (int i = tid; i < NTOK * HD / 4; i += 288) {
        int n = i >> 3, d0 = (i & 7) * 4;
        *(float4*)(sq + n * QVS + d0) = *(const float4*)(qp + n * HD + d0);
        *(float4*)(sk + n * QVS + d0) = *(const float4*)(kp + n * HD + d0);
        float4 vv = *(const float4*)(vp + n * HD + d0);
        int np = vperm(n);
        svt[(d0 + 0) * VTS + np] = vv.x;
        svt[(d0 + 1) * VTS + np] = vv.y;
        svt[(d0 + 2) * VTS + np] = vv.z;
        svt[(d0 + 3) * VTS + np] = vv.w;
    }
    __syncthreads();

    // ---- init accumulators with bias + mask (loads overlap the MMA chain) ----
    const float* bp = g_bias + (long)(w * NH + h) * NTOK * NTOK;
    const float* mp = mask + (long)bw * NTOK * NTOK;
    int r0 = m0 + gp, r1 = r0 + 8;
    float acc[18][4];
#pragma unroll
    for (int t = 0; t < 18; ++t) {
        int mcol = t * 8 + 2 * tg;
        float2 b0 = __ldg((const float2*)(bp + r0 * NTOK + mcol));
        float2 b1 = __ldg((const float2*)(bp + r1 * NTOK + mcol));
        float2 q0 = __ldg((const float2*)(mp + r0 * NTOK + mcol));
        float2 q1 = __ldg((const float2*)(mp + r1 * NTOK + mcol));
        acc[t][0] = b0.x + q0.x;
        acc[t][1] = b0.y + q0.y;
        acc[t][2] = b1.x + q1.x;
        acc[t][3] = b1.y + q1.y;
    }

    // ---- QK^T: full 16x144 per warp in registers (accumulates onto bias+mask) ----
#pragma unroll
    for (int kk = 0; kk < 4; ++kk) {
        int k = kk * 8;
        const float* ab = sq + (m0 + gp) * QVS + k + tg;
        uint32_t a0 = __float_as_uint(ab[0]);
        uint32_t a1 = __float_as_uint(ab[8 * QVS]);
        uint32_t a2 = __float_as_uint(ab[4]);
        uint32_t a3 = __float_as_uint(ab[8 * QVS + 4]);
#pragma unroll
        for (int t = 0; t < 18; ++t) {
            const float* bb = sk + (t * 8 + gp) * QVS + k + tg;
            mma_tf32(acc[t], a0, a1, a2, a3,
                     __float_as_uint(bb[0]), __float_as_uint(bb[4]));
        }
    }

    // ---- softmax in registers (rows r0: slots 0,1 ; r1: slots 2,3) ----
    float mx0 = -1e30f, mx1 = -1e30f;
#pragma unroll
    for (int t = 0; t < 18; ++t) {
        mx0 = fmaxf(mx0, fmaxf(acc[t][0], acc[t][1]));
        mx1 = fmaxf(mx1, fmaxf(acc[t][2], acc[t][3]));
    }
    mx0 = fmaxf(mx0, __shfl_xor_sync(0xffffffffu, mx0, 1));
    mx0 = fmaxf(mx0, __shfl_xor_sync(0xffffffffu, mx0, 2));
    mx1 = fmaxf(mx1, __shfl_xor_sync(0xffffffffu, mx1, 1));
    mx1 = fmaxf(mx1, __shfl_xor_sync(0xffffffffu, mx1, 2));
    float s0 = 0.f, s1 = 0.f;
#pragma unroll
    for (int t = 0; t < 18; ++t) {
        acc[t][0] = __expf(acc[t][0] - mx0); s0 += acc[t][0];
        acc[t][1] = __expf(acc[t][1] - mx0); s0 += acc[t][1];
        acc[t][2] = __expf(acc[t][2] - mx1); s1 += acc[t][2];
        acc[t][3] = __expf(acc[t][3] - mx1); s1 += acc[t][3];
    }
    s0 += __shfl_xor_sync(0xffffffffu, s0, 1);
    s0 += __shfl_xor_sync(0xffffffffu, s0, 2);
    s1 += __shfl_xor_sync(0xffffffffu, s1, 1);
    s1 += __shfl_xor_sync(0xffffffffu, s1, 2);
    float inv0 = 1.f / s0, inv1 = 1.f / s1;
#pragma unroll
    for (int t = 0; t < 18; ++t) {
        acc[t][0] = f2tff(acc[t][0] * inv0);
        acc[t][1] = f2tff(acc[t][1] * inv0);
        acc[t][2] = f2tff(acc[t][2] * inv1);
        acc[t][3] = f2tff(acc[t][3] * inv1);
    }

    // ---- P @ V: A fragments straight from acc (C-layout == A-layout under vperm) ----
    float acc2[4][4];
#pragma unroll
    for (int t = 0; t < 4; t++)
#pragma unroll
        for (int j = 0; j < 4; j++) acc2[t][j] = 0.f;
#pragma unroll
    for (int t = 0; t < 18; ++t) {
        uint32_t a0 = __float_as_uint(acc[t][0]);
        uint32_t a1 = __float_as_uint(acc[t][2]);
        uint32_t a2 = __float_as_uint(acc[t][1]);
        uint32_t a3 = __float_as_uint(acc[t][3]);
        int k0 = t * 8;
#pragma unroll
        for (int nt = 0; nt < 4; ++nt) {
            const float* bb = svt + (nt * 8 + gp) * VTS + k0 + tg;
            mma_tf32(acc2[nt], a0, a1, a2, a3,
                     __float_as_uint(bb[0]), __float_as_uint(bb[4]));
        }
    }
    // ---- store to fragment-direct g_o2, tf32-rounded ----
    // element o[r][c] (c = h*32 + nt*8 + 2tg + cc) lives at
    //   g_o2f[ (((bw*24 + c/8)*NTOK + r)*4 + ((2tg+cc)&3))*2 + (tg>>1) ]
    float* g_o2f = g_o2;
    int slot = tg >> 1;
#pragma unroll
    for (int nt = 0; nt < 4; ++nt) {
        int kkb = (h * HD + nt * 8) >> 3;   // kk group for this 8-col block
#pragma unroll
        for (int cc = 0; cc < 2; ++cc) {
            int tg2 = (2 * tg + cc) & 3;
            long i0 = (((long)(bw * 24 + kkb) * NTOK + r0) * 4 + tg2) * 2 + slot;
            long i1 = (((long)(bw * 24 + kkb) * NTOK + r1) * 4 + tg2) * 2 + slot;
            g_o2f[i0] = f2tff(acc2[nt][cc]);
            g_o2f[i1] = f2tff(acc2[nt][2 + cc]);
        }
    }
}

// ---------------- kernel 3: output projection (A + B both direct, no smem) ----------
__global__ __launch_bounds__(288, 2) void proj_kernel(
    const float* __restrict__ bias, float* __restrict__ out) {
    int bw = blockIdx.x;
    int tid = threadIdx.x;
    int warp = tid >> 5, lane = tid & 31, gp = lane >> 2, tg = lane & 3;
    int m0 = warp * 16;

    const float2* ao = (const float2*)g_o2 + (long)bw * 24 * NTOK * 4;
    const float2* wp = (const float2*)g_wproj;
    for (int ct = 0; ct < 3; ++ct) {
        float acc[8][4];
#pragma unroll
        for (int t = 0; t < 8; t++)
#pragma unroll
            for (int j = 0; j < 4; j++) acc[t][j] = 0.f;
#pragma unroll 2
        for (int kk = 0; kk < 24; ++kk) {
            float2 pa0 = __ldg(ao + ((long)kk * NTOK + m0 + gp) * 4 + tg);
            float2 pa1 = __ldg(ao + ((long)kk * NTOK + m0 + gp + 8) * 4 + tg);
            uint32_t a0 = __float_as_uint(pa0.x), a2 = __float_as_uint(pa0.y);
            uint32_t a1 = __float_as_uint(pa1.x), a3 = __float_as_uint(pa1.y);
            const float2* wb = wp + (ct * 24 + kk) * 256 + lane;
#pragma unroll
            for (int t = 0; t < 8; ++t) {
                float2 pb = __ldg(wb + t * 32);
                mma_tf32(acc[t], a0, a1, a2, a3,
                         __float_as_uint(pb.x), __float_as_uint(pb.y));
            }
        }
        int c0 = ct * 64;
        float* ob = out + (long)bw * NTOK * CDIM;
#pragma unroll
        for (int t = 0; t < 8; ++t) {
#pragma unroll
            for (int cc = 0; cc < 2; ++cc) {
                int col = c0 + t * 8 + 2 * tg + cc;
                float bb = bias[col];
                ob[(m0 + gp) * CDIM + col]     = acc[t][cc]     + bb;
                ob[(m0 + gp + 8) * CDIM + col] = acc[t][2 + cc] + bb;
            }
        }
    }
}

// ---------------- launch ----------------
extern "C" void kernel_launch(void* const* d_in, const int* in_sizes, int n_in,
                              void* d_out, int out_size) {
    const float* x      = (const float*)d_in[0];
    const float* mask   = (const float*)d_in[1];
    const float* qkv_w  = (const float*)d_in[2];
    const float* qkv_b  = (const float*)d_in[3];
    const float* proj_w = (const float*)d_in[4];
    const float* proj_b = (const float*)d_in[5];
    const float* table  = (const float*)d_in[6];
    const int*   pos    = (const int*)d_in[7];
    float* out = (float*)d_out;

    const int lin_smem  = NTOK * SXS * 4;                          // 115200 B
    const int attn_smem = (2 * NTOK * QVS + HD * VTS) * 4;         // 65024 B
    cudaFuncSetAttribute(qkv_kernel,  cudaFuncAttributeMaxDynamicSharedMemorySize, lin_smem);
    cudaFuncSetAttribute(attn_kernel, cudaFuncAttributeMaxDynamicSharedMemorySize, attn_smem);

    float* wqkv_ptr;  cudaGetSymbolAddress((void**)&wqkv_ptr,  g_wqkv);
    float* wproj_ptr; cudaGetSymbolAddress((void**)&wproj_ptr, g_wproj);

    bias_pre_kernel<<<(NTOK * NTOK) / 32, 256>>>(table, pos);
    wperm_kernel<<<(9 * 24 * 8 * 8 * 4 + 255) / 256, 256>>>(qkv_w,  wqkv_ptr, 9);
    wperm_kernel<<<(3 * 24 * 8 * 8 * 4 + 255) / 256, 256>>>(proj_w, wproj_ptr, 3);
    qkv_kernel<<<NBW, 288, lin_smem>>>(x, qkv_b);
    attn_kernel<<<dim3(NH, NBW), 288, attn_smem>>>(mask);
    proj_kernel<<<NBW, 288>>>(proj_b, out);
}